// round 1
// baseline (speedup 1.0000x reference)
#include <cuda_runtime.h>
#include <cstddef>

#define N_NODES 50000
#define E_MAX   1700000

// ---------------- scratch (device globals; no runtime allocation) ------------
__device__ float g_bufA[(size_t)N_NODES * 512];
__device__ float g_bufB[(size_t)N_NODES * 512];
__device__ int   g_row_ptr[N_NODES + 1];
__device__ int   g_col[E_MAX];
__device__ int   g_cursor[N_NODES];
__device__ int   g_in_deg[N_NODES];
__device__ int   g_out_deg[N_NODES];
__device__ float g_inv_den[N_NODES];   // 1/(in_deg+1)   (SAGE 'gcn')
__device__ float g_inv_src[N_NODES];   // out_deg^-1/2   (GraphConv)
__device__ float g_inv_dst[N_NODES];   // in_deg^-1/2    (GraphConv)

// ---------------- CSR construction ------------------------------------------
__global__ void k_zero_deg() {
    int i = blockIdx.x * blockDim.x + threadIdx.x;
    if (i < N_NODES) { g_in_deg[i] = 0; g_out_deg[i] = 0; }
}

__global__ void k_count(const int* __restrict__ src, const int* __restrict__ dst, int E) {
    int e = blockIdx.x * blockDim.x + threadIdx.x;
    if (e < E) {
        atomicAdd(&g_in_deg[dst[e]], 1);
        atomicAdd(&g_out_deg[src[e]], 1);
    }
}

// single-block chunked Hillis-Steele scan over in_deg -> row_ptr (exclusive)
__global__ void k_scan() {
    __shared__ int s[1024];
    __shared__ int carry;
    int tid = threadIdx.x;
    if (tid == 0) { carry = 0; g_row_ptr[0] = 0; }
    __syncthreads();
    for (int base = 0; base < N_NODES; base += 1024) {
        int idx = base + tid;
        int v = (idx < N_NODES) ? g_in_deg[idx] : 0;
        s[tid] = v;
        __syncthreads();
        for (int off = 1; off < 1024; off <<= 1) {
            int t = (tid >= off) ? s[tid - off] : 0;
            __syncthreads();
            s[tid] += t;
            __syncthreads();
        }
        if (idx < N_NODES) g_row_ptr[idx + 1] = carry + s[tid];
        __syncthreads();
        if (tid == 0) carry += s[1023];
        __syncthreads();
    }
}

__global__ void k_scalers() {
    int i = blockIdx.x * blockDim.x + threadIdx.x;
    if (i < N_NODES) {
        int ind  = g_in_deg[i];
        int outd = g_out_deg[i];
        g_cursor[i]  = g_row_ptr[i];
        g_inv_den[i] = 1.0f / (float)(ind + 1);
        g_inv_src[i] = rsqrtf((float)(outd > 0 ? outd : 1));
        g_inv_dst[i] = rsqrtf((float)(ind  > 0 ? ind  : 1));
    }
}

__global__ void k_fill(const int* __restrict__ src, const int* __restrict__ dst, int E) {
    int e = blockIdx.x * blockDim.x + threadIdx.x;
    if (e < E) {
        int p = atomicAdd(&g_cursor[dst[e]], 1);
        g_col[p] = src[e];
    }
}

// ---------------- aggregation (one block per dst node) -----------------------
// GC=false : x[i] = (sum_{e->i} h[src] + h[i]) * inv_den[i]           (SAGE)
// GC=true  : x[i] = inv_dst[i] * sum_{e->i} inv_src[src]*h[src]       (GraphConv)
template <int DIM, bool GC>
__global__ void k_agg(const float* __restrict__ h, float* __restrict__ x) {
    const int i   = blockIdx.x;
    const int tid = threadIdx.x;
    constexpr int NF = DIM / 128;
    float acc[NF];
#pragma unroll
    for (int j = 0; j < NF; ++j) acc[j] = 0.f;

    const int start = g_row_ptr[i];
    const int end   = g_row_ptr[i + 1];
    for (int e = start; e < end; ++e) {
        const int s = g_col[e];
        const float* hr = h + (size_t)s * DIM;
        if (GC) {
            const float w = g_inv_src[s];
#pragma unroll
            for (int j = 0; j < NF; ++j) acc[j] += w * hr[tid + j * 128];
        } else {
#pragma unroll
            for (int j = 0; j < NF; ++j) acc[j] += hr[tid + j * 128];
        }
    }

    float* xo = x + (size_t)i * DIM;
    if (GC) {
        const float w = g_inv_dst[i];
#pragma unroll
        for (int j = 0; j < NF; ++j) xo[tid + j * 128] = acc[j] * w;
    } else {
        const float w = g_inv_den[i];
        const float* hi = h + (size_t)i * DIM;
#pragma unroll
        for (int j = 0; j < NF; ++j) xo[tid + j * 128] = (acc[j] + hi[tid + j * 128]) * w;
    }
}

// ---------------- SGEMM: C[M,Nc] = A[M,K] * W[Nc,K]^T + bias (opt. relu) -----
// 128x128 block tile, BK=8, 256 threads, 8x8 microtile.
__global__ __launch_bounds__(256, 2)
void k_gemm(const float* __restrict__ A, const float* __restrict__ W,
            const float* __restrict__ bias, float* __restrict__ C,
            int M, int K, int Nc, int relu) {
    __shared__ float As[8][128];
    __shared__ float Ws[8][128];

    const int m0  = blockIdx.y * 128;
    const int n0  = blockIdx.x * 128;
    const int tid = threadIdx.x;
    const int tx  = tid & 15;       // 0..15 -> n microtile
    const int ty  = tid >> 4;       // 0..15 -> m microtile
    const int lRow = tid >> 1;      // 0..127
    const int lCol = (tid & 1) * 4; // 0 or 4

    float acc[8][8];
#pragma unroll
    for (int i = 0; i < 8; ++i)
#pragma unroll
        for (int j = 0; j < 8; ++j) acc[i][j] = 0.f;

    for (int kt = 0; kt < K; kt += 8) {
        float4 av = make_float4(0.f, 0.f, 0.f, 0.f);
        const int am = m0 + lRow;
        if (am < M) av = *(const float4*)(A + (size_t)am * K + kt + lCol);
        const float4 wv = *(const float4*)(W + (size_t)(n0 + lRow) * K + kt + lCol);

        __syncthreads();  // protect prior-iteration smem reads
        As[lCol + 0][lRow] = av.x; As[lCol + 1][lRow] = av.y;
        As[lCol + 2][lRow] = av.z; As[lCol + 3][lRow] = av.w;
        Ws[lCol + 0][lRow] = wv.x; Ws[lCol + 1][lRow] = wv.y;
        Ws[lCol + 2][lRow] = wv.z; Ws[lCol + 3][lRow] = wv.w;
        __syncthreads();

#pragma unroll
        for (int kk = 0; kk < 8; ++kk) {
            float ra[8], rb[8];
#pragma unroll
            for (int i = 0; i < 8; ++i) ra[i] = As[kk][ty * 8 + i];
#pragma unroll
            for (int j = 0; j < 8; ++j) rb[j] = Ws[kk][tx * 8 + j];
#pragma unroll
            for (int i = 0; i < 8; ++i)
#pragma unroll
                for (int j = 0; j < 8; ++j) acc[i][j] += ra[i] * rb[j];
        }
    }

#pragma unroll
    for (int i = 0; i < 8; ++i) {
        const int m = m0 + ty * 8 + i;
        if (m < M) {
#pragma unroll
            for (int j = 0; j < 8; ++j) {
                const int n = n0 + tx * 8 + j;
                float v = acc[i][j] + bias[n];
                if (relu) v = fmaxf(v, 0.f);
                C[(size_t)m * Nc + n] = v;
            }
        }
    }
}

// ---------------- host orchestration -----------------------------------------
static inline void launch_gemm(const float* A, const float* W, const float* b,
                               float* C, int K, int Nc, int relu) {
    dim3 grid(Nc / 128, (N_NODES + 127) / 128);
    k_gemm<<<grid, 256>>>(A, W, b, C, N_NODES, K, Nc, relu);
}

extern "C" void kernel_launch(void* const* d_in, const int* in_sizes, int n_in,
                              void* d_out, int out_size) {
    const float* features = (const float*)d_in[0];
    const int*   src      = (const int*)d_in[1];
    const int*   dst      = (const int*)d_in[2];
    const float* sw0 = (const float*)d_in[3];  const float* sb0 = (const float*)d_in[4];
    const float* gw0 = (const float*)d_in[5];  const float* gb0 = (const float*)d_in[6];
    const float* sw1 = (const float*)d_in[7];  const float* sb1 = (const float*)d_in[8];
    const float* gw1 = (const float*)d_in[9];  const float* gb1 = (const float*)d_in[10];
    const float* sw2 = (const float*)d_in[11]; const float* sb2 = (const float*)d_in[12];
    const float* gw2 = (const float*)d_in[13]; const float* gb2 = (const float*)d_in[14];
    const float* fcw = (const float*)d_in[15]; const float* fcb = (const float*)d_in[16];
    const int E = in_sizes[1];

    float* bufA = nullptr;
    float* bufB = nullptr;
    cudaGetSymbolAddress((void**)&bufA, g_bufA);
    cudaGetSymbolAddress((void**)&bufB, g_bufB);

    // ---- CSR build ----
    k_zero_deg<<<(N_NODES + 255) / 256, 256>>>();
    k_count<<<(E + 255) / 256, 256>>>(src, dst, E);
    k_scan<<<1, 1024>>>();
    k_scalers<<<(N_NODES + 255) / 256, 256>>>();
    k_fill<<<(E + 255) / 256, 256>>>(src, dst, E);

    // ---- stage 0: 512 -> 384 ----
    k_agg<512, false><<<N_NODES, 128>>>(features, bufA);
    launch_gemm(bufA, sw0, sb0, bufB, 512, 384, 1);
    k_agg<384, true><<<N_NODES, 128>>>(bufB, bufA);
    launch_gemm(bufA, gw0, gb0, bufB, 384, 384, 1);

    // ---- stage 1: 384 -> 256 ----
    k_agg<384, false><<<N_NODES, 128>>>(bufB, bufA);
    launch_gemm(bufA, sw1, sb1, bufB, 384, 256, 1);
    k_agg<256, true><<<N_NODES, 128>>>(bufB, bufA);
    launch_gemm(bufA, gw1, gb1, bufB, 256, 256, 1);

    // ---- stage 2: 256 -> 128 ----
    k_agg<256, false><<<N_NODES, 128>>>(bufB, bufA);
    launch_gemm(bufA, sw2, sb2, bufB, 256, 128, 1);
    k_agg<128, true><<<N_NODES, 128>>>(bufB, bufA);
    launch_gemm(bufA, gw2, gb2, bufB, 128, 128, 1);

    // ---- final FC: 128 -> 128 (no relu) ----
    launch_gemm(bufB, fcw, fcb, (float*)d_out, 128, 128, 0);
}

// round 2
// speedup vs baseline: 1.2808x; 1.2808x over previous
#include <cuda_runtime.h>
#include <cstddef>

#define N_NODES 50000
#define E_MAX   1700000

// ---------------- scratch (device globals; no runtime allocation) ------------
__device__ float g_bufA[(size_t)N_NODES * 512];
__device__ float g_bufB[(size_t)N_NODES * 512];
__device__ int   g_row_ptr[N_NODES + 1];
__device__ int   g_col[E_MAX];
__device__ int   g_cursor[N_NODES];
__device__ int   g_in_deg[N_NODES];
__device__ int   g_out_deg[N_NODES];
__device__ float g_inv_den[N_NODES];   // 1/(in_deg+1)   (SAGE 'gcn')
__device__ float g_inv_src[N_NODES];   // out_deg^-1/2   (GraphConv)
__device__ float g_inv_dst[N_NODES];   // in_deg^-1/2    (GraphConv)

// ---------------- CSR construction ------------------------------------------
__global__ void k_zero_deg() {
    int i = blockIdx.x * blockDim.x + threadIdx.x;
    if (i < N_NODES) { g_in_deg[i] = 0; g_out_deg[i] = 0; }
}

__global__ void k_count(const int* __restrict__ src, const int* __restrict__ dst, int E) {
    int e = blockIdx.x * blockDim.x + threadIdx.x;
    if (e < E) {
        atomicAdd(&g_in_deg[dst[e]], 1);
        atomicAdd(&g_out_deg[src[e]], 1);
    }
}

// single-block chunked scan (warp-shuffle based) in_deg -> row_ptr (exclusive)
__global__ void k_scan() {
    __shared__ int wsum[32];
    __shared__ int carry;
    const int tid  = threadIdx.x;
    const int lane = tid & 31;
    const int w    = tid >> 5;
    if (tid == 0) { carry = 0; g_row_ptr[0] = 0; }
    __syncthreads();
    for (int base = 0; base < N_NODES; base += 1024) {
        int idx = base + tid;
        int v = (idx < N_NODES) ? g_in_deg[idx] : 0;
        int x = v;
#pragma unroll
        for (int off = 1; off < 32; off <<= 1) {
            int t = __shfl_up_sync(0xffffffffu, x, off);
            if (lane >= off) x += t;
        }
        if (lane == 31) wsum[w] = x;
        __syncthreads();
        if (w == 0) {
            int s = wsum[lane];
#pragma unroll
            for (int off = 1; off < 32; off <<= 1) {
                int t = __shfl_up_sync(0xffffffffu, s, off);
                if (lane >= off) s += t;
            }
            wsum[lane] = s;
        }
        __syncthreads();
        int total  = wsum[31];
        int prefix = carry + (w > 0 ? wsum[w - 1] : 0) + x;  // inclusive
        if (idx < N_NODES) g_row_ptr[idx + 1] = prefix;
        __syncthreads();
        if (tid == 0) carry += total;
        __syncthreads();
    }
}

__global__ void k_scalers() {
    int i = blockIdx.x * blockDim.x + threadIdx.x;
    if (i < N_NODES) {
        int ind  = g_in_deg[i];
        int outd = g_out_deg[i];
        g_cursor[i]  = g_row_ptr[i];
        g_inv_den[i] = 1.0f / (float)(ind + 1);
        g_inv_src[i] = rsqrtf((float)(outd > 0 ? outd : 1));
        g_inv_dst[i] = rsqrtf((float)(ind  > 0 ? ind  : 1));
    }
}

__global__ void k_fill(const int* __restrict__ src, const int* __restrict__ dst, int E) {
    int e = blockIdx.x * blockDim.x + threadIdx.x;
    if (e < E) {
        int p = atomicAdd(&g_cursor[dst[e]], 1);
        g_col[p] = src[e];
    }
}

// ---------------- aggregation: one WARP per dst node, float4 lanes -----------
// Input y = h @ W^T (linear part already applied). Epilogue fuses bias + relu.
// GC=false (SAGE): out_i = relu((sum_{e->i} y_s + y_i) * inv_den_i + b)
// GC=true  (GCN) : out_i = relu(inv_dst_i * sum_{e->i} inv_src_s * y_s + b)
template <int DIM, bool GC>
__global__ void k_agg(const float* __restrict__ y, float* __restrict__ x,
                      const float* __restrict__ bias) {
    const int gwarp = (blockIdx.x * blockDim.x + threadIdx.x) >> 5;
    if (gwarp >= N_NODES) return;
    const int lane = threadIdx.x & 31;
    constexpr int NF = DIM / 128;   // float4 chunks per lane

    float4 acc[NF];
#pragma unroll
    for (int j = 0; j < NF; ++j) acc[j] = make_float4(0.f, 0.f, 0.f, 0.f);

    const int start = g_row_ptr[gwarp];
    const int end   = g_row_ptr[gwarp + 1];
    for (int e = start; e < end; ++e) {
        const int s = g_col[e];
        const float4* yr = (const float4*)(y + (size_t)s * DIM);
        if (GC) {
            const float w = g_inv_src[s];
#pragma unroll
            for (int j = 0; j < NF; ++j) {
                float4 v = yr[lane + j * 32];
                acc[j].x += w * v.x; acc[j].y += w * v.y;
                acc[j].z += w * v.z; acc[j].w += w * v.w;
            }
        } else {
#pragma unroll
            for (int j = 0; j < NF; ++j) {
                float4 v = yr[lane + j * 32];
                acc[j].x += v.x; acc[j].y += v.y;
                acc[j].z += v.z; acc[j].w += v.w;
            }
        }
    }

    const float4* b4 = (const float4*)bias;
    float4* xo = (float4*)(x + (size_t)gwarp * DIM);
    if (GC) {
        const float w = g_inv_dst[gwarp];
#pragma unroll
        for (int j = 0; j < NF; ++j) {
            float4 b = b4[lane + j * 32];
            float4 o;
            o.x = fmaxf(acc[j].x * w + b.x, 0.f);
            o.y = fmaxf(acc[j].y * w + b.y, 0.f);
            o.z = fmaxf(acc[j].z * w + b.z, 0.f);
            o.w = fmaxf(acc[j].w * w + b.w, 0.f);
            xo[lane + j * 32] = o;
        }
    } else {
        const float w = g_inv_den[gwarp];
        const float4* yi = (const float4*)(y + (size_t)gwarp * DIM);
#pragma unroll
        for (int j = 0; j < NF; ++j) {
            float4 b = b4[lane + j * 32];
            float4 s = yi[lane + j * 32];
            float4 o;
            o.x = fmaxf((acc[j].x + s.x) * w + b.x, 0.f);
            o.y = fmaxf((acc[j].y + s.y) * w + b.y, 0.f);
            o.z = fmaxf((acc[j].z + s.z) * w + b.z, 0.f);
            o.w = fmaxf((acc[j].w + s.w) * w + b.w, 0.f);
            xo[lane + j * 32] = o;
        }
    }
}

// ---------------- SGEMM: C[M,Nc] = A[M,K] * W[Nc,K]^T (+bias) ----------------
// 128x128 tile, BK=8 double-buffered, 256 threads, 8x8 microtile.
__global__ __launch_bounds__(256, 2)
void k_gemm(const float* __restrict__ A, const float* __restrict__ W,
            const float* __restrict__ bias, float* __restrict__ C,
            int M, int K, int Nc) {
    __shared__ float As[2][8][128];
    __shared__ float Ws[2][8][128];

    const int m0  = blockIdx.y * 128;
    const int n0  = blockIdx.x * 128;
    const int tid = threadIdx.x;
    const int tx  = tid & 15;
    const int ty  = tid >> 4;
    const int lRow = tid >> 1;
    const int lCol = (tid & 1) * 4;
    const int am = m0 + lRow;

    float acc[8][8];
#pragma unroll
    for (int i = 0; i < 8; ++i)
#pragma unroll
        for (int j = 0; j < 8; ++j) acc[i][j] = 0.f;

    // prologue: tile kt=0
    float4 av = make_float4(0.f, 0.f, 0.f, 0.f);
    if (am < M) av = *(const float4*)(A + (size_t)am * K + lCol);
    float4 wv = *(const float4*)(W + (size_t)(n0 + lRow) * K + lCol);
    As[0][lCol + 0][lRow] = av.x; As[0][lCol + 1][lRow] = av.y;
    As[0][lCol + 2][lRow] = av.z; As[0][lCol + 3][lRow] = av.w;
    Ws[0][lCol + 0][lRow] = wv.x; Ws[0][lCol + 1][lRow] = wv.y;
    Ws[0][lCol + 2][lRow] = wv.z; Ws[0][lCol + 3][lRow] = wv.w;
    __syncthreads();

    int buf = 0;
    for (int kt = 8; kt < K; kt += 8) {
        float4 av2 = make_float4(0.f, 0.f, 0.f, 0.f);
        if (am < M) av2 = *(const float4*)(A + (size_t)am * K + kt + lCol);
        float4 wv2 = *(const float4*)(W + (size_t)(n0 + lRow) * K + kt + lCol);

#pragma unroll
        for (int kk = 0; kk < 8; ++kk) {
            float ra[8], rb[8];
#pragma unroll
            for (int i = 0; i < 8; ++i) ra[i] = As[buf][kk][ty * 8 + i];
#pragma unroll
            for (int j = 0; j < 8; ++j) rb[j] = Ws[buf][kk][tx * 8 + j];
#pragma unroll
            for (int i = 0; i < 8; ++i)
#pragma unroll
                for (int j = 0; j < 8; ++j) acc[i][j] += ra[i] * rb[j];
        }

        const int nb = buf ^ 1;
        As[nb][lCol + 0][lRow] = av2.x; As[nb][lCol + 1][lRow] = av2.y;
        As[nb][lCol + 2][lRow] = av2.z; As[nb][lCol + 3][lRow] = av2.w;
        Ws[nb][lCol + 0][lRow] = wv2.x; Ws[nb][lCol + 1][lRow] = wv2.y;
        Ws[nb][lCol + 2][lRow] = wv2.z; Ws[nb][lCol + 3][lRow] = wv2.w;
        __syncthreads();
        buf = nb;
    }

#pragma unroll
    for (int kk = 0; kk < 8; ++kk) {
        float ra[8], rb[8];
#pragma unroll
        for (int i = 0; i < 8; ++i) ra[i] = As[buf][kk][ty * 8 + i];
#pragma unroll
        for (int j = 0; j < 8; ++j) rb[j] = Ws[buf][kk][tx * 8 + j];
#pragma unroll
        for (int i = 0; i < 8; ++i)
#pragma unroll
            for (int j = 0; j < 8; ++j) acc[i][j] += ra[i] * rb[j];
    }

#pragma unroll
    for (int i = 0; i < 8; ++i) {
        const int m = m0 + ty * 8 + i;
        if (m < M) {
#pragma unroll
            for (int j = 0; j < 8; ++j) {
                const int n = n0 + tx * 8 + j;
                float v = acc[i][j];
                if (bias) v += bias[n];
                C[(size_t)m * Nc + n] = v;
            }
        }
    }
}

// ---------------- host orchestration -----------------------------------------
static inline void launch_gemm(const float* A, const float* W, const float* b,
                               float* C, int K, int Nc) {
    dim3 grid(Nc / 128, (N_NODES + 127) / 128);
    k_gemm<<<grid, 256>>>(A, W, b, C, N_NODES, K, Nc);
}

template <int DIM, bool GC>
static inline void launch_agg(const float* y, float* x, const float* bias) {
    // 8 warps (8 nodes) per 256-thread block
    int blocks = (N_NODES + 7) / 8;
    k_agg<DIM, GC><<<blocks, 256>>>(y, x, bias);
}

extern "C" void kernel_launch(void* const* d_in, const int* in_sizes, int n_in,
                              void* d_out, int out_size) {
    const float* features = (const float*)d_in[0];
    const int*   src      = (const int*)d_in[1];
    const int*   dst      = (const int*)d_in[2];
    const float* sw0 = (const float*)d_in[3];  const float* sb0 = (const float*)d_in[4];
    const float* gw0 = (const float*)d_in[5];  const float* gb0 = (const float*)d_in[6];
    const float* sw1 = (const float*)d_in[7];  const float* sb1 = (const float*)d_in[8];
    const float* gw1 = (const float*)d_in[9];  const float* gb1 = (const float*)d_in[10];
    const float* sw2 = (const float*)d_in[11]; const float* sb2 = (const float*)d_in[12];
    const float* gw2 = (const float*)d_in[13]; const float* gb2 = (const float*)d_in[14];
    const float* fcw = (const float*)d_in[15]; const float* fcb = (const float*)d_in[16];
    const int E = in_sizes[1];

    float* bufA = nullptr;
    float* bufB = nullptr;
    cudaGetSymbolAddress((void**)&bufA, g_bufA);
    cudaGetSymbolAddress((void**)&bufB, g_bufB);

    // ---- CSR build ----
    k_zero_deg<<<(N_NODES + 255) / 256, 256>>>();
    k_count<<<(E + 255) / 256, 256>>>(src, dst, E);
    k_scan<<<1, 1024>>>();
    k_scalers<<<(N_NODES + 255) / 256, 256>>>();
    k_fill<<<(E + 255) / 256, 256>>>(src, dst, E);

    // ---- stage 0: 512 -> 384 ----  (GEMM first, aggregate in output dim)
    launch_gemm(features, sw0, nullptr, bufA, 512, 384);
    launch_agg<384, false>(bufA, bufB, sb0);
    launch_gemm(bufB, gw0, nullptr, bufA, 384, 384);
    launch_agg<384, true>(bufA, bufB, gb0);

    // ---- stage 1: 384 -> 256 ----
    launch_gemm(bufB, sw1, nullptr, bufA, 384, 256);
    launch_agg<256, false>(bufA, bufB, sb1);
    launch_gemm(bufB, gw1, nullptr, bufA, 256, 256);
    launch_agg<256, true>(bufA, bufB, gb1);

    // ---- stage 2: 256 -> 128 ----
    launch_gemm(bufB, sw2, nullptr, bufA, 256, 128);
    launch_agg<128, false>(bufA, bufB, sb2);
    launch_gemm(bufB, gw2, nullptr, bufA, 128, 128);
    launch_agg<128, true>(bufA, bufB, gb2);

    // ---- final FC: 128 -> 128 (bias, no relu) ----
    launch_gemm(bufB, fcw, fcb, (float*)d_out, 128, 128);
}

// round 3
// speedup vs baseline: 1.4310x; 1.1173x over previous
#include <cuda_runtime.h>
#include <cstddef>

#define N_NODES 50000
#define E_MAX   1700000

// ---------------- scratch (device globals; no runtime allocation) ------------
__device__ float g_bufA[(size_t)N_NODES * 512];
__device__ float g_bufB[(size_t)N_NODES * 512];
__device__ int   g_row_ptr[N_NODES + 1];
__device__ int   g_col[E_MAX];
__device__ int   g_cursor[N_NODES];
__device__ int   g_in_deg[N_NODES];
__device__ int   g_out_deg[N_NODES];
__device__ float g_inv_den[N_NODES];   // 1/(in_deg+1)   (SAGE 'gcn')
__device__ float g_inv_src[N_NODES];   // out_deg^-1/2   (GraphConv)
__device__ float g_inv_dst[N_NODES];   // in_deg^-1/2    (GraphConv)

// ---------------- packed f32x2 helpers ---------------------------------------
__device__ __forceinline__ unsigned long long ffma2(unsigned long long a,
                                                    unsigned long long b,
                                                    unsigned long long c) {
    unsigned long long d;
    asm("fma.rn.f32x2 %0, %1, %2, %3;" : "=l"(d) : "l"(a), "l"(b), "l"(c));
    return d;
}
__device__ __forceinline__ unsigned long long dup_f32(float x) {
    unsigned long long r;
    asm("mov.b64 %0, {%1, %1};" : "=l"(r) : "f"(x));
    return r;
}
__device__ __forceinline__ float lo_f32(unsigned long long v) {
    return __uint_as_float((unsigned int)v);
}
__device__ __forceinline__ float hi_f32(unsigned long long v) {
    return __uint_as_float((unsigned int)(v >> 32));
}

// ---------------- CSR construction ------------------------------------------
__global__ void k_zero_deg() {
    int i = blockIdx.x * blockDim.x + threadIdx.x;
    if (i < N_NODES) { g_in_deg[i] = 0; g_out_deg[i] = 0; }
}

__global__ void k_count(const int* __restrict__ src, const int* __restrict__ dst, int E) {
    int e = blockIdx.x * blockDim.x + threadIdx.x;
    if (e < E) {
        atomicAdd(&g_in_deg[dst[e]], 1);
        atomicAdd(&g_out_deg[src[e]], 1);
    }
}

// single-block chunked scan (warp-shuffle based) in_deg -> row_ptr (exclusive)
__global__ void k_scan() {
    __shared__ int wsum[32];
    __shared__ int carry;
    const int tid  = threadIdx.x;
    const int lane = tid & 31;
    const int w    = tid >> 5;
    if (tid == 0) { carry = 0; g_row_ptr[0] = 0; }
    __syncthreads();
    for (int base = 0; base < N_NODES; base += 1024) {
        int idx = base + tid;
        int v = (idx < N_NODES) ? g_in_deg[idx] : 0;
        int x = v;
#pragma unroll
        for (int off = 1; off < 32; off <<= 1) {
            int t = __shfl_up_sync(0xffffffffu, x, off);
            if (lane >= off) x += t;
        }
        if (lane == 31) wsum[w] = x;
        __syncthreads();
        if (w == 0) {
            int s = wsum[lane];
#pragma unroll
            for (int off = 1; off < 32; off <<= 1) {
                int t = __shfl_up_sync(0xffffffffu, s, off);
                if (lane >= off) s += t;
            }
            wsum[lane] = s;
        }
        __syncthreads();
        int total  = wsum[31];
        int prefix = carry + (w > 0 ? wsum[w - 1] : 0) + x;  // inclusive
        if (idx < N_NODES) g_row_ptr[idx + 1] = prefix;
        __syncthreads();
        if (tid == 0) carry += total;
        __syncthreads();
    }
}

__global__ void k_scalers() {
    int i = blockIdx.x * blockDim.x + threadIdx.x;
    if (i < N_NODES) {
        int ind  = g_in_deg[i];
        int outd = g_out_deg[i];
        g_cursor[i]  = g_row_ptr[i];
        g_inv_den[i] = 1.0f / (float)(ind + 1);
        g_inv_src[i] = rsqrtf((float)(outd > 0 ? outd : 1));
        g_inv_dst[i] = rsqrtf((float)(ind  > 0 ? ind  : 1));
    }
}

__global__ void k_fill(const int* __restrict__ src, const int* __restrict__ dst, int E) {
    int e = blockIdx.x * blockDim.x + threadIdx.x;
    if (e < E) {
        int p = atomicAdd(&g_cursor[dst[e]], 1);
        g_col[p] = src[e];
    }
}

// ---------------- aggregation: one WARP per dst node, float4 lanes -----------
// Input y = h @ W^T (linear part already applied). Epilogue fuses bias + relu.
// GC=false (SAGE): out_i = relu((sum_{e->i} y_s + y_i) * inv_den_i + b)
// GC=true  (GCN) : out_i = relu(inv_dst_i * sum_{e->i} inv_src_s * y_s + b)
template <int DIM, bool GC>
__global__ void k_agg(const float* __restrict__ y, float* __restrict__ x,
                      const float* __restrict__ bias) {
    const int gwarp = (blockIdx.x * blockDim.x + threadIdx.x) >> 5;
    if (gwarp >= N_NODES) return;
    const int lane = threadIdx.x & 31;
    constexpr int NF = DIM / 128;   // float4 chunks per lane

    float4 acc[NF];
#pragma unroll
    for (int j = 0; j < NF; ++j) acc[j] = make_float4(0.f, 0.f, 0.f, 0.f);

    const int start = g_row_ptr[gwarp];
    const int end   = g_row_ptr[gwarp + 1];
    for (int e = start; e < end; ++e) {
        const int s = g_col[e];
        const float4* yr = (const float4*)(y + (size_t)s * DIM);
        if (GC) {
            const float w = g_inv_src[s];
#pragma unroll
            for (int j = 0; j < NF; ++j) {
                float4 v = yr[lane + j * 32];
                acc[j].x += w * v.x; acc[j].y += w * v.y;
                acc[j].z += w * v.z; acc[j].w += w * v.w;
            }
        } else {
#pragma unroll
            for (int j = 0; j < NF; ++j) {
                float4 v = yr[lane + j * 32];
                acc[j].x += v.x; acc[j].y += v.y;
                acc[j].z += v.z; acc[j].w += v.w;
            }
        }
    }

    const float4* b4 = (const float4*)bias;
    float4* xo = (float4*)(x + (size_t)gwarp * DIM);
    if (GC) {
        const float w = g_inv_dst[gwarp];
#pragma unroll
        for (int j = 0; j < NF; ++j) {
            float4 b = b4[lane + j * 32];
            float4 o;
            o.x = fmaxf(acc[j].x * w + b.x, 0.f);
            o.y = fmaxf(acc[j].y * w + b.y, 0.f);
            o.z = fmaxf(acc[j].z * w + b.z, 0.f);
            o.w = fmaxf(acc[j].w * w + b.w, 0.f);
            xo[lane + j * 32] = o;
        }
    } else {
        const float w = g_inv_den[gwarp];
        const float4* yi = (const float4*)(y + (size_t)gwarp * DIM);
#pragma unroll
        for (int j = 0; j < NF; ++j) {
            float4 b = b4[lane + j * 32];
            float4 s = yi[lane + j * 32];
            float4 o;
            o.x = fmaxf((acc[j].x + s.x) * w + b.x, 0.f);
            o.y = fmaxf((acc[j].y + s.y) * w + b.y, 0.f);
            o.z = fmaxf((acc[j].z + s.z) * w + b.z, 0.f);
            o.w = fmaxf((acc[j].w + s.w) * w + b.w, 0.f);
            xo[lane + j * 32] = o;
        }
    }
}

// ---------------- SGEMM: C[M,Nc] = A[M,K] * W[Nc,K]^T (+bias) ----------------
// 128x128 tile, BK=8 double-buffered, 256 threads, 8x8 microtile.
// Inner product uses packed fp32x2 FMA (SASS FFMA2): 32 FFMA2 per k-step
// instead of 64 FFMA. Bit-identical numerics to scalar fp32 FMA.
__global__ __launch_bounds__(256, 2)
void k_gemm(const float* __restrict__ A, const float* __restrict__ W,
            const float* __restrict__ bias, float* __restrict__ C,
            int M, int K, int Nc) {
    __shared__ float As[2][8][128];
    __shared__ float Ws[2][8][128];

    const int m0  = blockIdx.y * 128;
    const int n0  = blockIdx.x * 128;
    const int tid = threadIdx.x;
    const int tx  = tid & 15;
    const int ty  = tid >> 4;
    const int lRow = tid >> 1;
    const int lCol = (tid & 1) * 4;
    const int am = m0 + lRow;

    // acc2[i][j2] holds C(m0+ty*8+i, n0+tx*8+2*j2 .. +1) as packed f32x2
    unsigned long long acc2[8][4];
    const unsigned long long z2 = dup_f32(0.f);
#pragma unroll
    for (int i = 0; i < 8; ++i)
#pragma unroll
        for (int j = 0; j < 4; ++j) acc2[i][j] = z2;

    // prologue: tile kt=0
    float4 av = make_float4(0.f, 0.f, 0.f, 0.f);
    if (am < M) av = *(const float4*)(A + (size_t)am * K + lCol);
    float4 wv = *(const float4*)(W + (size_t)(n0 + lRow) * K + lCol);
    As[0][lCol + 0][lRow] = av.x; As[0][lCol + 1][lRow] = av.y;
    As[0][lCol + 2][lRow] = av.z; As[0][lCol + 3][lRow] = av.w;
    Ws[0][lCol + 0][lRow] = wv.x; Ws[0][lCol + 1][lRow] = wv.y;
    Ws[0][lCol + 2][lRow] = wv.z; Ws[0][lCol + 3][lRow] = wv.w;
    __syncthreads();

    int buf = 0;
    for (int kt = 8; kt < K; kt += 8) {
        float4 av2 = make_float4(0.f, 0.f, 0.f, 0.f);
        if (am < M) av2 = *(const float4*)(A + (size_t)am * K + kt + lCol);
        float4 wv2 = *(const float4*)(W + (size_t)(n0 + lRow) * K + kt + lCol);

#pragma unroll
        for (int kk = 0; kk < 8; ++kk) {
            const float4 a0 = *(const float4*)&As[buf][kk][ty * 8];
            const float4 a1 = *(const float4*)&As[buf][kk][ty * 8 + 4];
            const ulonglong2 b0 = *(const ulonglong2*)&Ws[buf][kk][tx * 8];
            const ulonglong2 b1 = *(const ulonglong2*)&Ws[buf][kk][tx * 8 + 4];
            const unsigned long long rb[4] = {b0.x, b0.y, b1.x, b1.y};
            const float ra[8] = {a0.x, a0.y, a0.z, a0.w, a1.x, a1.y, a1.z, a1.w};
#pragma unroll
            for (int i = 0; i < 8; ++i) {
                const unsigned long long rd = dup_f32(ra[i]);
#pragma unroll
                for (int j = 0; j < 4; ++j) acc2[i][j] = ffma2(rd, rb[j], acc2[i][j]);
            }
        }

        const int nb = buf ^ 1;
        As[nb][lCol + 0][lRow] = av2.x; As[nb][lCol + 1][lRow] = av2.y;
        As[nb][lCol + 2][lRow] = av2.z; As[nb][lCol + 3][lRow] = av2.w;
        Ws[nb][lCol + 0][lRow] = wv2.x; Ws[nb][lCol + 1][lRow] = wv2.y;
        Ws[nb][lCol + 2][lRow] = wv2.z; Ws[nb][lCol + 3][lRow] = wv2.w;
        __syncthreads();
        buf = nb;
    }

#pragma unroll
    for (int kk = 0; kk < 8; ++kk) {
        const float4 a0 = *(const float4*)&As[buf][kk][ty * 8];
        const float4 a1 = *(const float4*)&As[buf][kk][ty * 8 + 4];
        const ulonglong2 b0 = *(const ulonglong2*)&Ws[buf][kk][tx * 8];
        const ulonglong2 b1 = *(const ulonglong2*)&Ws[buf][kk][tx * 8 + 4];
        const unsigned long long rb[4] = {b0.x, b0.y, b1.x, b1.y};
        const float ra[8] = {a0.x, a0.y, a0.z, a0.w, a1.x, a1.y, a1.z, a1.w};
#pragma unroll
        for (int i = 0; i < 8; ++i) {
            const unsigned long long rd = dup_f32(ra[i]);
#pragma unroll
            for (int j = 0; j < 4; ++j) acc2[i][j] = ffma2(rd, rb[j], acc2[i][j]);
        }
    }

#pragma unroll
    for (int i = 0; i < 8; ++i) {
        const int m = m0 + ty * 8 + i;
        if (m < M) {
            float4 o0, o1;
            o0.x = lo_f32(acc2[i][0]); o0.y = hi_f32(acc2[i][0]);
            o0.z = lo_f32(acc2[i][1]); o0.w = hi_f32(acc2[i][1]);
            o1.x = lo_f32(acc2[i][2]); o1.y = hi_f32(acc2[i][2]);
            o1.z = lo_f32(acc2[i][3]); o1.w = hi_f32(acc2[i][3]);
            const int n = n0 + tx * 8;
            if (bias) {
                const float4 bb0 = *(const float4*)(bias + n);
                const float4 bb1 = *(const float4*)(bias + n + 4);
                o0.x += bb0.x; o0.y += bb0.y; o0.z += bb0.z; o0.w += bb0.w;
                o1.x += bb1.x; o1.y += bb1.y; o1.z += bb1.z; o1.w += bb1.w;
            }
            *(float4*)(C + (size_t)m * Nc + n)     = o0;
            *(float4*)(C + (size_t)m * Nc + n + 4) = o1;
        }
    }
}

// ---------------- host orchestration -----------------------------------------
static inline void launch_gemm(const float* A, const float* W, const float* b,
                               float* C, int K, int Nc) {
    dim3 grid(Nc / 128, (N_NODES + 127) / 128);
    k_gemm<<<grid, 256>>>(A, W, b, C, N_NODES, K, Nc);
}

template <int DIM, bool GC>
static inline void launch_agg(const float* y, float* x, const float* bias) {
    int blocks = (N_NODES + 7) / 8;   // 8 warps (nodes) per 256-thread block
    k_agg<DIM, GC><<<blocks, 256>>>(y, x, bias);
}

extern "C" void kernel_launch(void* const* d_in, const int* in_sizes, int n_in,
                              void* d_out, int out_size) {
    const float* features = (const float*)d_in[0];
    const int*   src      = (const int*)d_in[1];
    const int*   dst      = (const int*)d_in[2];
    const float* sw0 = (const float*)d_in[3];  const float* sb0 = (const float*)d_in[4];
    const float* gw0 = (const float*)d_in[5];  const float* gb0 = (const float*)d_in[6];
    const float* sw1 = (const float*)d_in[7];  const float* sb1 = (const float*)d_in[8];
    const float* gw1 = (const float*)d_in[9];  const float* gb1 = (const float*)d_in[10];
    const float* sw2 = (const float*)d_in[11]; const float* sb2 = (const float*)d_in[12];
    const float* gw2 = (const float*)d_in[13]; const float* gb2 = (const float*)d_in[14];
    const float* fcw = (const float*)d_in[15]; const float* fcb = (const float*)d_in[16];
    const int E = in_sizes[1];

    float* bufA = nullptr;
    float* bufB = nullptr;
    cudaGetSymbolAddress((void**)&bufA, g_bufA);
    cudaGetSymbolAddress((void**)&bufB, g_bufB);

    // ---- CSR build ----
    k_zero_deg<<<(N_NODES + 255) / 256, 256>>>();
    k_count<<<(E + 255) / 256, 256>>>(src, dst, E);
    k_scan<<<1, 1024>>>();
    k_scalers<<<(N_NODES + 255) / 256, 256>>>();
    k_fill<<<(E + 255) / 256, 256>>>(src, dst, E);

    // ---- stage 0: 512 -> 384 ----  (GEMM first, aggregate in output dim)
    launch_gemm(features, sw0, nullptr, bufA, 512, 384);
    launch_agg<384, false>(bufA, bufB, sb0);
    launch_gemm(bufB, gw0, nullptr, bufA, 384, 384);
    launch_agg<384, true>(bufA, bufB, gb0);

    // ---- stage 1: 384 -> 256 ----
    launch_gemm(bufB, sw1, nullptr, bufA, 384, 256);
    launch_agg<256, false>(bufA, bufB, sb1);
    launch_gemm(bufB, gw1, nullptr, bufA, 256, 256);
    launch_agg<256, true>(bufA, bufB, gb1);

    // ---- stage 2: 256 -> 128 ----
    launch_gemm(bufB, sw2, nullptr, bufA, 256, 128);
    launch_agg<128, false>(bufA, bufB, sb2);
    launch_gemm(bufB, gw2, nullptr, bufA, 128, 128);
    launch_agg<128, true>(bufA, bufB, gb2);

    // ---- final FC: 128 -> 128 (bias, no relu) ----
    launch_gemm(bufB, fcw, fcb, (float*)d_out, 128, 128);
}

// round 6
// speedup vs baseline: 2.4633x; 1.7214x over previous
#include <cuda_runtime.h>
#include <cuda_bf16.h>
#include <cstddef>
#include <cstdint>

#define N_NODES 50000
#define E_MAX   1700000
#define W_TOTAL 573440

// ---------------- scratch (device globals; no runtime allocation) ------------
__device__ float         g_bufA[(size_t)N_NODES * 384];   // fp32 GEMM outputs
__device__ __nv_bfloat16 g_hi[(size_t)N_NODES * 512];     // split-bf16 activations
__device__ __nv_bfloat16 g_lo[(size_t)N_NODES * 512];
__device__ __nv_bfloat16 g_whi[W_TOTAL];
__device__ __nv_bfloat16 g_wlo[W_TOTAL];
__device__ int   g_row_ptr[N_NODES + 1];
__device__ int   g_col[E_MAX];
__device__ int   g_cursor[N_NODES];
__device__ int   g_in_deg[N_NODES];
__device__ int   g_out_deg[N_NODES];
__device__ float g_inv_den[N_NODES];
__device__ float g_inv_src[N_NODES];
__device__ float g_inv_dst[N_NODES];

// ---------------- helpers -----------------------------------------------------
__device__ __forceinline__ uint32_t smem_u32(const void* p) {
    uint32_t a;
    asm("{ .reg .u64 t; cvta.to.shared.u64 t, %1; cvt.u32.u64 %0, t; }" : "=r"(a) : "l"(p));
    return a;
}
__device__ __forceinline__ void ldsm4(uint32_t* r, uint32_t addr) {
    asm volatile("ldmatrix.sync.aligned.m8n8.x4.shared.b16 {%0,%1,%2,%3}, [%4];"
        : "=r"(r[0]), "=r"(r[1]), "=r"(r[2]), "=r"(r[3]) : "r"(addr));
}
__device__ __forceinline__ void mma16816(float* c, const uint32_t* a, const uint32_t* b) {
    asm volatile("mma.sync.aligned.m16n8k16.row.col.f32.bf16.bf16.f32 "
        "{%0,%1,%2,%3}, {%4,%5,%6,%7}, {%8,%9}, {%0,%1,%2,%3};"
        : "+f"(c[0]), "+f"(c[1]), "+f"(c[2]), "+f"(c[3])
        : "r"(a[0]), "r"(a[1]), "r"(a[2]), "r"(a[3]), "r"(b[0]), "r"(b[1]));
}
__device__ __forceinline__ void cp16(uint32_t smem, const void* g, int srcsz) {
    asm volatile("cp.async.cg.shared.global [%0], [%1], 16, %2;"
        :: "r"(smem), "l"(g), "r"(srcsz) : "memory");
}
__device__ __forceinline__ void split_bf16(float v, __nv_bfloat16& h, __nv_bfloat16& l) {
    h = __float2bfloat16_rn(v);
    l = __float2bfloat16_rn(v - __bfloat162float(h));
}

// ---------------- CSR construction ------------------------------------------
__global__ void k_zero_deg() {
    int i = blockIdx.x * blockDim.x + threadIdx.x;
    if (i < N_NODES) { g_in_deg[i] = 0; g_out_deg[i] = 0; }
}

__global__ void k_count(const int* __restrict__ src, const int* __restrict__ dst, int E) {
    int e = blockIdx.x * blockDim.x + threadIdx.x;
    if (e < E) {
        atomicAdd(&g_in_deg[dst[e]], 1);
        atomicAdd(&g_out_deg[src[e]], 1);
    }
}

__global__ void k_scan() {
    __shared__ int wsum[32];
    __shared__ int carry;
    const int tid  = threadIdx.x;
    const int lane = tid & 31;
    const int w    = tid >> 5;
    if (tid == 0) { carry = 0; g_row_ptr[0] = 0; }
    __syncthreads();
    for (int base = 0; base < N_NODES; base += 1024) {
        int idx = base + tid;
        int x = (idx < N_NODES) ? g_in_deg[idx] : 0;
#pragma unroll
        for (int off = 1; off < 32; off <<= 1) {
            int t = __shfl_up_sync(0xffffffffu, x, off);
            if (lane >= off) x += t;
        }
        if (lane == 31) wsum[w] = x;
        __syncthreads();
        if (w == 0) {
            int s = wsum[lane];
#pragma unroll
            for (int off = 1; off < 32; off <<= 1) {
                int t = __shfl_up_sync(0xffffffffu, s, off);
                if (lane >= off) s += t;
            }
            wsum[lane] = s;
        }
        __syncthreads();
        int total  = wsum[31];
        int prefix = carry + (w > 0 ? wsum[w - 1] : 0) + x;
        if (idx < N_NODES) g_row_ptr[idx + 1] = prefix;
        __syncthreads();
        if (tid == 0) carry += total;
        __syncthreads();
    }
}

__global__ void k_scalers() {
    int i = blockIdx.x * blockDim.x + threadIdx.x;
    if (i < N_NODES) {
        int ind  = g_in_deg[i];
        int outd = g_out_deg[i];
        g_cursor[i]  = g_row_ptr[i];
        g_inv_den[i] = 1.0f / (float)(ind + 1);
        g_inv_src[i] = rsqrtf((float)(outd > 0 ? outd : 1));
        g_inv_dst[i] = rsqrtf((float)(ind  > 0 ? ind  : 1));
    }
}

__global__ void k_fill(const int* __restrict__ src, const int* __restrict__ dst, int E) {
    int e = blockIdx.x * blockDim.x + threadIdx.x;
    if (e < E) {
        int p = atomicAdd(&g_cursor[dst[e]], 1);
        g_col[p] = src[e];
    }
}

// ---------------- converter ---------------------------------------------------
__global__ void k_convert(const float* __restrict__ x, __nv_bfloat16* __restrict__ hi,
                          __nv_bfloat16* __restrict__ lo, int n) {
    int i = blockIdx.x * blockDim.x + threadIdx.x;
    if (i < n) {
        __nv_bfloat16 h, l;
        split_bf16(x[i], h, l);
        hi[i] = h; lo[i] = l;
    }
}

// ---------------- aggregation: one WARP per dst node -------------------------
// Reads fp32 y = A@W^T; fuses bias+relu; writes split-bf16 (hi, lo).
template <int DIM, bool GC>
__global__ void k_agg(const float* __restrict__ y,
                      __nv_bfloat16* __restrict__ xh, __nv_bfloat16* __restrict__ xl,
                      const float* __restrict__ bias) {
    const int gwarp = (blockIdx.x * blockDim.x + threadIdx.x) >> 5;
    if (gwarp >= N_NODES) return;
    const int lane = threadIdx.x & 31;
    constexpr int NF = DIM / 128;

    float4 acc[NF];
#pragma unroll
    for (int j = 0; j < NF; ++j) acc[j] = make_float4(0.f, 0.f, 0.f, 0.f);

    const int start = g_row_ptr[gwarp];
    const int end   = g_row_ptr[gwarp + 1];
    for (int e = start; e < end; ++e) {
        const int s = g_col[e];
        const float4* yr = (const float4*)(y + (size_t)s * DIM);
        if (GC) {
            const float w = g_inv_src[s];
#pragma unroll
            for (int j = 0; j < NF; ++j) {
                float4 v = yr[lane + j * 32];
                acc[j].x += w * v.x; acc[j].y += w * v.y;
                acc[j].z += w * v.z; acc[j].w += w * v.w;
            }
        } else {
#pragma unroll
            for (int j = 0; j < NF; ++j) {
                float4 v = yr[lane + j * 32];
                acc[j].x += v.x; acc[j].y += v.y;
                acc[j].z += v.z; acc[j].w += v.w;
            }
        }
    }

    const float4* b4 = (const float4*)bias;
    __nv_bfloat16* xhr = xh + (size_t)gwarp * DIM;
    __nv_bfloat16* xlr = xl + (size_t)gwarp * DIM;
    const float wsc = GC ? g_inv_dst[gwarp] : g_inv_den[gwarp];
    const float4* yi = (const float4*)(y + (size_t)gwarp * DIM);
#pragma unroll
    for (int j = 0; j < NF; ++j) {
        float4 b = b4[lane + j * 32];
        float4 o;
        if (GC) {
            o.x = fmaxf(acc[j].x * wsc + b.x, 0.f);
            o.y = fmaxf(acc[j].y * wsc + b.y, 0.f);
            o.z = fmaxf(acc[j].z * wsc + b.z, 0.f);
            o.w = fmaxf(acc[j].w * wsc + b.w, 0.f);
        } else {
            float4 s = yi[lane + j * 32];
            o.x = fmaxf((acc[j].x + s.x) * wsc + b.x, 0.f);
            o.y = fmaxf((acc[j].y + s.y) * wsc + b.y, 0.f);
            o.z = fmaxf((acc[j].z + s.z) * wsc + b.z, 0.f);
            o.w = fmaxf((acc[j].w + s.w) * wsc + b.w, 0.f);
        }
        __nv_bfloat16 h0, h1, h2, h3, l0, l1, l2, l3;
        split_bf16(o.x, h0, l0); split_bf16(o.y, h1, l1);
        split_bf16(o.z, h2, l2); split_bf16(o.w, h3, l3);
        const int off = lane * 4 + j * 128;
        __nv_bfloat162* ph = (__nv_bfloat162*)(xhr + off);
        __nv_bfloat162* pl = (__nv_bfloat162*)(xlr + off);
        ph[0] = __nv_bfloat162(h0, h1); ph[1] = __nv_bfloat162(h2, h3);
        pl[0] = __nv_bfloat162(l0, l1); pl[1] = __nv_bfloat162(l2, l3);
    }
}

// ---------------- split-bf16 HMMA GEMM ----------------------------------------
// C[M,Nc] = A[M,K] @ W[Nc,K]^T (+bias), fp32 out.
// A ≈ Ahi+Alo, W ≈ Whi+Wlo: D = Ahi*Whi + Ahi*Wlo + Alo*Whi  (fp32 accum).
// 128x128 CTA tile, BK=64, 2-stage cp.async pipeline, 8 warps (2m x 4n),
// warp tile 64x32, mma.sync m16n8k16. SMEM: 128B pitch, chunk^=(row&7) swizzle.
#define T_AHI 0
#define T_ALO 16384
#define T_BHI 32768
#define T_BLO 49152
#define STAGE_BYTES 65536
#define GEMM_SMEM   131072

__global__ __launch_bounds__(256, 1)
void k_gemm_mma(const __nv_bfloat16* __restrict__ Ahi, const __nv_bfloat16* __restrict__ Alo,
                const __nv_bfloat16* __restrict__ Whi, const __nv_bfloat16* __restrict__ Wlo,
                const float* __restrict__ bias, float* __restrict__ C,
                int M, int K, int Nc) {
    extern __shared__ char sm[];
    const uint32_t sb = smem_u32(sm);
    const int tid  = threadIdx.x;
    const int wid  = tid >> 5;
    const int lane = tid & 31;
    const int wm = wid >> 2;          // 0..1  -> m offset wm*64
    const int wn = wid & 3;           // 0..3  -> n offset wn*32
    const int m0 = blockIdx.y * 128;
    const int n0 = blockIdx.x * 128;

    float acc[4][4][4];
#pragma unroll
    for (int i = 0; i < 4; ++i)
#pragma unroll
        for (int j = 0; j < 4; ++j)
#pragma unroll
            for (int q = 0; q < 4; ++q) acc[i][j][q] = 0.f;

    const int nch = K >> 6;

    // ---- cp.async chunk issue ----
    auto issue = [&](int ch) {
        const uint32_t so = sb + (uint32_t)(ch & 1) * STAGE_BYTES;
        const int kc0 = ch << 6;
#pragma unroll
        for (int it = 0; it < 4; ++it) {
            const int idx = tid + it * 256;      // 0..1023
            const int r = idx >> 3, c = idx & 7;
            const uint32_t sw = (uint32_t)(r * 128 + (((c ^ (r & 7)) & 7) << 4));
            const int gr = m0 + r;
            const int av = (gr < M) ? 16 : 0;
            const size_t aoff = (size_t)gr * K + kc0 + c * 8;
            cp16(so + T_AHI + sw, Ahi + aoff, av);
            cp16(so + T_ALO + sw, Alo + aoff, av);
            const size_t boff = (size_t)(n0 + r) * K + kc0 + c * 8;
            cp16(so + T_BHI + sw, Whi + boff, 16);
            cp16(so + T_BLO + sw, Wlo + boff, 16);
        }
        asm volatile("cp.async.commit_group;" ::: "memory");
    };

    issue(0);
    for (int ch = 0; ch < nch; ++ch) {
        if (ch + 1 < nch) {
            issue(ch + 1);
            asm volatile("cp.async.wait_group 1;" ::: "memory");
        } else {
            asm volatile("cp.async.wait_group 0;" ::: "memory");
        }
        __syncthreads();

        const uint32_t so = sb + (uint32_t)(ch & 1) * STAGE_BYTES;
#pragma unroll
        for (int kk = 0; kk < 64; kk += 16) {
            // A fragments: 4 m16 frags, hi & lo
            uint32_t ah[4][4], al[4][4];
            const int ar = (lane & 15);
            const int akb = kk + ((lane >> 4) << 3);
#pragma unroll
            for (int mi = 0; mi < 4; ++mi) {
                const int r = wm * 64 + mi * 16 + ar;
                const uint32_t off = (uint32_t)(r * 128 + ((((akb >> 3) ^ (r & 7)) & 7) << 4));
                ldsm4(ah[mi], so + T_AHI + off);
                ldsm4(al[mi], so + T_ALO + off);
            }
            // B fragments: 4 n8 frags via 2 ldsm4 (pair p -> frags 2p, 2p+1)
            uint32_t bh[2][4], bl[2][4];
            const int br = ((lane >> 4) << 3) + (lane & 7);
            const int bkb = kk + (((lane >> 3) & 1) << 3);
#pragma unroll
            for (int p = 0; p < 2; ++p) {
                const int r = wn * 32 + p * 16 + br;
                const uint32_t off = (uint32_t)(r * 128 + ((((bkb >> 3) ^ (r & 7)) & 7) << 4));
                ldsm4(bh[p], so + T_BHI + off);
                ldsm4(bl[p], so + T_BLO + off);
            }
#pragma unroll
            for (int mi = 0; mi < 4; ++mi) {
#pragma unroll
                for (int j = 0; j < 4; ++j) {
                    const uint32_t* pbh = &bh[j >> 1][(j & 1) * 2];
                    const uint32_t* pbl = &bl[j >> 1][(j & 1) * 2];
                    mma16816(acc[mi][j], ah[mi], pbh);
                    mma16816(acc[mi][j], ah[mi], pbl);
                    mma16816(acc[mi][j], al[mi], pbh);
                }
            }
        }
        __syncthreads();   // stage reuse safety before next issue overwrites
    }

    // ---- epilogue ----
    const int gid  = lane >> 2;
    const int tidx = lane & 3;
#pragma unroll
    for (int mi = 0; mi < 4; ++mi) {
        const int row = m0 + wm * 64 + mi * 16 + gid;
#pragma unroll
        for (int j = 0; j < 4; ++j) {
            const int col = n0 + wn * 32 + j * 8 + tidx * 2;
            float b0 = 0.f, b1 = 0.f;
            if (bias) { b0 = bias[col]; b1 = bias[col + 1]; }
            if (row < M) {
                float2 v0 = make_float2(acc[mi][j][0] + b0, acc[mi][j][1] + b1);
                *(float2*)(C + (size_t)row * Nc + col) = v0;
            }
            if (row + 8 < M) {
                float2 v1 = make_float2(acc[mi][j][2] + b0, acc[mi][j][3] + b1);
                *(float2*)(C + (size_t)(row + 8) * Nc + col) = v1;
            }
        }
    }
}

// ---------------- host orchestration -----------------------------------------
static inline void launch_gemm(const __nv_bfloat16* ah, const __nv_bfloat16* al,
                               const __nv_bfloat16* wh, const __nv_bfloat16* wl,
                               const float* b, float* C, int K, int Nc) {
    dim3 grid(Nc / 128, (N_NODES + 127) / 128);
    k_gemm_mma<<<grid, 256, GEMM_SMEM>>>(ah, al, wh, wl, b, C, N_NODES, K, Nc);
}

template <int DIM, bool GC>
static inline void launch_agg(const float* y, __nv_bfloat16* xh, __nv_bfloat16* xl,
                              const float* bias) {
    int blocks = (N_NODES + 7) / 8;
    k_agg<DIM, GC><<<blocks, 256>>>(y, xh, xl, bias);
}

extern "C" void kernel_launch(void* const* d_in, const int* in_sizes, int n_in,
                              void* d_out, int out_size) {
    const float* features = (const float*)d_in[0];
    const int*   src      = (const int*)d_in[1];
    const int*   dst      = (const int*)d_in[2];
    const float* sw0 = (const float*)d_in[3];  const float* sb0 = (const float*)d_in[4];
    const float* gw0 = (const float*)d_in[5];  const float* gb0 = (const float*)d_in[6];
    const float* sw1 = (const float*)d_in[7];  const float* sb1 = (const float*)d_in[8];
    const float* gw1 = (const float*)d_in[9];  const float* gb1 = (const float*)d_in[10];
    const float* sw2 = (const float*)d_in[11]; const float* sb2 = (const float*)d_in[12];
    const float* gw2 = (const float*)d_in[13]; const float* gb2 = (const float*)d_in[14];
    const float* fcw = (const float*)d_in[15]; const float* fcb = (const float*)d_in[16];
    const int E = in_sizes[1];

    cudaFuncSetAttribute(k_gemm_mma, cudaFuncAttributeMaxDynamicSharedMemorySize, GEMM_SMEM);

    float* bufA = nullptr;
    __nv_bfloat16 *hi = nullptr, *lo = nullptr, *whi = nullptr, *wlo = nullptr;
    cudaGetSymbolAddress((void**)&bufA, g_bufA);
    cudaGetSymbolAddress((void**)&hi,   g_hi);
    cudaGetSymbolAddress((void**)&lo,   g_lo);
    cudaGetSymbolAddress((void**)&whi,  g_whi);
    cudaGetSymbolAddress((void**)&wlo,  g_wlo);

    const int O_SW0 = 0,      O_GW0 = 196608, O_SW1 = 344064, O_GW1 = 442368;
    const int O_SW2 = 507904, O_GW2 = 540672, O_FC  = 557056;

    // ---- CSR build ----
    k_zero_deg<<<(N_NODES + 255) / 256, 256>>>();
    k_count<<<(E + 255) / 256, 256>>>(src, dst, E);
    k_scan<<<1, 1024>>>();
    k_scalers<<<(N_NODES + 255) / 256, 256>>>();
    k_fill<<<(E + 255) / 256, 256>>>(src, dst, E);

    // ---- converts: features + all 7 weight matrices -> split bf16 ----
    k_convert<<<(N_NODES * 512 + 255) / 256, 256>>>(features, hi, lo, N_NODES * 512);
    k_convert<<<(196608 + 255) / 256, 256>>>(sw0, whi + O_SW0, wlo + O_SW0, 196608);
    k_convert<<<(147456 + 255) / 256, 256>>>(gw0, whi + O_GW0, wlo + O_GW0, 147456);
    k_convert<<<( 98304 + 255) / 256, 256>>>(sw1, whi + O_SW1, wlo + O_SW1,  98304);
    k_convert<<<( 65536 + 255) / 256, 256>>>(gw1, whi + O_GW1, wlo + O_GW1,  65536);
    k_convert<<<( 32768 + 255) / 256, 256>>>(sw2, whi + O_SW2, wlo + O_SW2,  32768);
    k_convert<<<( 16384 + 255) / 256, 256>>>(gw2, whi + O_GW2, wlo + O_GW2,  16384);
    k_convert<<<( 16384 + 255) / 256, 256>>>(fcw, whi + O_FC,  wlo + O_FC,   16384);

    // ---- stage 0: 512 -> 384 ----
    launch_gemm(hi, lo, whi + O_SW0, wlo + O_SW0, nullptr, bufA, 512, 384);
    launch_agg<384, false>(bufA, hi, lo, sb0);
    launch_gemm(hi, lo, whi + O_GW0, wlo + O_GW0, nullptr, bufA, 384, 384);
    launch_agg<384, true>(bufA, hi, lo, gb0);

    // ---- stage 1: 384 -> 256 ----
    launch_gemm(hi, lo, whi + O_SW1, wlo + O_SW1, nullptr, bufA, 384, 256);
    launch_agg<256, false>(bufA, hi, lo, sb1);
    launch_gemm(hi, lo, whi + O_GW1, wlo + O_GW1, nullptr, bufA, 256, 256);
    launch_agg<256, true>(bufA, hi, lo, gb1);

    // ---- stage 2: 256 -> 128 ----
    launch_gemm(hi, lo, whi + O_SW2, wlo + O_SW2, nullptr, bufA, 256, 128);
    launch_agg<128, false>(bufA, hi, lo, sb2);
    launch_gemm(hi, lo, whi + O_GW2, wlo + O_GW2, nullptr, bufA, 128, 128);
    launch_agg<128, true>(bufA, hi, lo, gb2);

    // ---- final FC: 128 -> 128 (bias, no relu) ----
    launch_gemm(hi, lo, whi + O_FC, wlo + O_FC, fcb, (float*)d_out, 128, 128);
}

// round 8
// speedup vs baseline: 2.8843x; 1.1709x over previous
#include <cuda_runtime.h>
#include <cuda_bf16.h>
#include <cuda_fp16.h>
#include <cstddef>
#include <cstdint>

#define N_NODES 50000
#define E_MAX   1700000
#define W_TOTAL 573440

// ---------------- scratch (device globals; no runtime allocation) ------------
__device__ __half        g_y[(size_t)N_NODES * 384];      // fp16 GEMM outputs
__device__ __nv_bfloat16 g_hi[(size_t)N_NODES * 512];     // split-bf16 activations
__device__ __nv_bfloat16 g_lo[(size_t)N_NODES * 512];
__device__ __nv_bfloat16 g_whi[W_TOTAL];
__device__ __nv_bfloat16 g_wlo[W_TOTAL];
__device__ int   g_row_ptr[N_NODES + 1];
__device__ int   g_col[E_MAX];
__device__ int   g_cursor[N_NODES];
__device__ int   g_in_deg[N_NODES];
__device__ int   g_out_deg[N_NODES];
__device__ float g_inv_den[N_NODES];
__device__ float g_inv_src[N_NODES];
__device__ float g_inv_dst[N_NODES];

// ---------------- helpers -----------------------------------------------------
__device__ __forceinline__ uint32_t smem_u32(const void* p) {
    uint32_t a;
    asm("{ .reg .u64 t; cvta.to.shared.u64 t, %1; cvt.u32.u64 %0, t; }" : "=r"(a) : "l"(p));
    return a;
}
__device__ __forceinline__ void ldsm4(uint32_t* r, uint32_t addr) {
    asm volatile("ldmatrix.sync.aligned.m8n8.x4.shared.b16 {%0,%1,%2,%3}, [%4];"
        : "=r"(r[0]), "=r"(r[1]), "=r"(r[2]), "=r"(r[3]) : "r"(addr));
}
__device__ __forceinline__ void mma16816(float* c, const uint32_t* a, const uint32_t* b) {
    asm volatile("mma.sync.aligned.m16n8k16.row.col.f32.bf16.bf16.f32 "
        "{%0,%1,%2,%3}, {%4,%5,%6,%7}, {%8,%9}, {%0,%1,%2,%3};"
        : "+f"(c[0]), "+f"(c[1]), "+f"(c[2]), "+f"(c[3])
        : "r"(a[0]), "r"(a[1]), "r"(a[2]), "r"(a[3]), "r"(b[0]), "r"(b[1]));
}
__device__ __forceinline__ void cp16(uint32_t smem, const void* g, int srcsz) {
    asm volatile("cp.async.cg.shared.global [%0], [%1], 16, %2;"
        :: "r"(smem), "l"(g), "r"(srcsz) : "memory");
}
__device__ __forceinline__ void split_bf16(float v, __nv_bfloat16& h, __nv_bfloat16& l) {
    h = __float2bfloat16_rn(v);
    l = __float2bfloat16_rn(v - __bfloat162float(h));
}

// ---------------- CSR construction ------------------------------------------
__global__ void k_zero_deg() {
    int i = blockIdx.x * blockDim.x + threadIdx.x;
    if (i < N_NODES) { g_in_deg[i] = 0; g_out_deg[i] = 0; }
}

__global__ void k_count(const int* __restrict__ src, const int* __restrict__ dst, int E) {
    int e = blockIdx.x * blockDim.x + threadIdx.x;
    if (e < E) {
        atomicAdd(&g_in_deg[dst[e]], 1);
        atomicAdd(&g_out_deg[src[e]], 1);
    }
}

__global__ void k_scan() {
    __shared__ int wsum[32];
    __shared__ int carry;
    const int tid  = threadIdx.x;
    const int lane = tid & 31;
    const int w    = tid >> 5;
    if (tid == 0) { carry = 0; g_row_ptr[0] = 0; }
    __syncthreads();
    for (int base = 0; base < N_NODES; base += 1024) {
        int idx = base + tid;
        int x = (idx < N_NODES) ? g_in_deg[idx] : 0;
#pragma unroll
        for (int off = 1; off < 32; off <<= 1) {
            int t = __shfl_up_sync(0xffffffffu, x, off);
            if (lane >= off) x += t;
        }
        if (lane == 31) wsum[w] = x;
        __syncthreads();
        if (w == 0) {
            int s = wsum[lane];
#pragma unroll
            for (int off = 1; off < 32; off <<= 1) {
                int t = __shfl_up_sync(0xffffffffu, s, off);
                if (lane >= off) s += t;
            }
            wsum[lane] = s;
        }
        __syncthreads();
        int total  = wsum[31];
        int prefix = carry + (w > 0 ? wsum[w - 1] : 0) + x;
        if (idx < N_NODES) g_row_ptr[idx + 1] = prefix;
        __syncthreads();
        if (tid == 0) carry += total;
        __syncthreads();
    }
}

__global__ void k_scalers() {
    int i = blockIdx.x * blockDim.x + threadIdx.x;
    if (i < N_NODES) {
        int ind  = g_in_deg[i];
        int outd = g_out_deg[i];
        g_cursor[i]  = g_row_ptr[i];
        g_inv_den[i] = 1.0f / (float)(ind + 1);
        g_inv_src[i] = rsqrtf((float)(outd > 0 ? outd : 1));
        g_inv_dst[i] = rsqrtf((float)(ind  > 0 ? ind  : 1));
    }
}

__global__ void k_fill(const int* __restrict__ src, const int* __restrict__ dst, int E) {
    int e = blockIdx.x * blockDim.x + threadIdx.x;
    if (e < E) {
        int p = atomicAdd(&g_cursor[dst[e]], 1);
        g_col[p] = src[e];
    }
}

// ---------------- converter ---------------------------------------------------
__global__ void k_convert(const float* __restrict__ x, __nv_bfloat16* __restrict__ hi,
                          __nv_bfloat16* __restrict__ lo, int n) {
    int i = blockIdx.x * blockDim.x + threadIdx.x;
    if (i < n) {
        __nv_bfloat16 h, l;
        split_bf16(x[i], h, l);
        hi[i] = h; lo[i] = l;
    }
}

// ---------------- aggregation: one WARP per dst node, fp16 gathers -----------
// y (fp16) = GEMM output. Accumulate fp32, fuse bias+relu, emit split-bf16.
// GC=false (SAGE): out_i = relu((sum y_s + y_i) * inv_den_i + b)
// GC=true  (GCN) : out_i = relu(inv_dst_i * sum inv_src_s * y_s + b)
template <int DIM, bool GC>
__global__ void k_agg(const __half* __restrict__ y,
                      __nv_bfloat16* __restrict__ xh, __nv_bfloat16* __restrict__ xl,
                      const float* __restrict__ bias) {
    const int gwarp = (blockIdx.x * blockDim.x + threadIdx.x) >> 5;
    if (gwarp >= N_NODES) return;
    const int lane = threadIdx.x & 31;
    constexpr int NF = DIM / 128;   // 4 halfs (uint2) per lane per chunk

    float4 acc[NF];
#pragma unroll
    for (int j = 0; j < NF; ++j) acc[j] = make_float4(0.f, 0.f, 0.f, 0.f);

    const int start = g_row_ptr[gwarp];
    const int end   = g_row_ptr[gwarp + 1];

    auto accum_row = [&](int s, float w) {
        const uint2* yr = (const uint2*)(y + (size_t)s * DIM);
#pragma unroll
        for (int j = 0; j < NF; ++j) {
            uint2 v = yr[lane + j * 32];
            float2 f0 = __half22float2(*reinterpret_cast<const __half2*>(&v.x));
            float2 f1 = __half22float2(*reinterpret_cast<const __half2*>(&v.y));
            if (GC) {
                acc[j].x += w * f0.x; acc[j].y += w * f0.y;
                acc[j].z += w * f1.x; acc[j].w += w * f1.y;
            } else {
                acc[j].x += f0.x; acc[j].y += f0.y;
                acc[j].z += f1.x; acc[j].w += f1.y;
            }
        }
    };

    int e = start;
    for (; e + 1 < end; e += 2) {     // 2-way unroll for MLP
        const int s0 = g_col[e];
        const int s1 = g_col[e + 1];
        const float w0 = GC ? g_inv_src[s0] : 0.f;
        const float w1 = GC ? g_inv_src[s1] : 0.f;
        accum_row(s0, w0);
        accum_row(s1, w1);
    }
    if (e < end) {
        const int s0 = g_col[e];
        accum_row(s0, GC ? g_inv_src[s0] : 0.f);
    }

    const float4* b4 = (const float4*)bias;
    __nv_bfloat16* xhr = xh + (size_t)gwarp * DIM;
    __nv_bfloat16* xlr = xl + (size_t)gwarp * DIM;
    const float wsc = GC ? g_inv_dst[gwarp] : g_inv_den[gwarp];
    const uint2* yi = (const uint2*)(y + (size_t)gwarp * DIM);
#pragma unroll
    for (int j = 0; j < NF; ++j) {
        float4 b = b4[lane + j * 32];
        float4 o;
        if (GC) {
            o.x = fmaxf(acc[j].x * wsc + b.x, 0.f);
            o.y = fmaxf(acc[j].y * wsc + b.y, 0.f);
            o.z = fmaxf(acc[j].z * wsc + b.z, 0.f);
            o.w = fmaxf(acc[j].w * wsc + b.w, 0.f);
        } else {
            uint2 v = yi[lane + j * 32];
            float2 s0 = __half22float2(*reinterpret_cast<const __half2*>(&v.x));
            float2 s1 = __half22float2(*reinterpret_cast<const __half2*>(&v.y));
            o.x = fmaxf((acc[j].x + s0.x) * wsc + b.x, 0.f);
            o.y = fmaxf((acc[j].y + s0.y) * wsc + b.y, 0.f);
            o.z = fmaxf((acc[j].z + s1.x) * wsc + b.z, 0.f);
            o.w = fmaxf((acc[j].w + s1.y) * wsc + b.w, 0.f);
        }
        __nv_bfloat16 h0, h1, h2, h3, l0, l1, l2, l3;
        split_bf16(o.x, h0, l0); split_bf16(o.y, h1, l1);
        split_bf16(o.z, h2, l2); split_bf16(o.w, h3, l3);
        const int off = lane * 4 + j * 128;
        __nv_bfloat162* ph = (__nv_bfloat162*)(xhr + off);
        __nv_bfloat162* pl = (__nv_bfloat162*)(xlr + off);
        ph[0] = __nv_bfloat162(h0, h1); ph[1] = __nv_bfloat162(h2, h3);
        pl[0] = __nv_bfloat162(l0, l1); pl[1] = __nv_bfloat162(l2, l3);
    }
}

// ---------------- split-bf16 HMMA GEMM ----------------------------------------
// C = A[M,K] @ W[Nc,K]^T. Writes fp16 y (Ch) or fp32+bias (Cf, final FC).
#define T_AHI 0
#define T_ALO 16384
#define T_BHI 32768
#define T_BLO 49152
#define STAGE_BYTES 65536
#define GEMM_SMEM   131072

__global__ __launch_bounds__(256, 1)
void k_gemm_mma(const __nv_bfloat16* __restrict__ Ahi, const __nv_bfloat16* __restrict__ Alo,
                const __nv_bfloat16* __restrict__ Whi, const __nv_bfloat16* __restrict__ Wlo,
                const float* __restrict__ bias, __half* __restrict__ Ch,
                float* __restrict__ Cf, int M, int K, int Nc) {
    extern __shared__ char sm[];
    const uint32_t sb = smem_u32(sm);
    const int tid  = threadIdx.x;
    const int wid  = tid >> 5;
    const int lane = tid & 31;
    const int wm = wid >> 2;
    const int wn = wid & 3;
    const int m0 = blockIdx.y * 128;
    const int n0 = blockIdx.x * 128;

    float acc[4][4][4];
#pragma unroll
    for (int i = 0; i < 4; ++i)
#pragma unroll
        for (int j = 0; j < 4; ++j)
#pragma unroll
            for (int q = 0; q < 4; ++q) acc[i][j][q] = 0.f;

    const int nch = K >> 6;

    auto issue = [&](int ch) {
        const uint32_t so = sb + (uint32_t)(ch & 1) * STAGE_BYTES;
        const int kc0 = ch << 6;
#pragma unroll
        for (int it = 0; it < 4; ++it) {
            const int idx = tid + it * 256;
            const int r = idx >> 3, c = idx & 7;
            const uint32_t sw = (uint32_t)(r * 128 + (((c ^ (r & 7)) & 7) << 4));
            const int gr = m0 + r;
            const int av = (gr < M) ? 16 : 0;
            const size_t aoff = (size_t)gr * K + kc0 + c * 8;
            cp16(so + T_AHI + sw, Ahi + aoff, av);
            cp16(so + T_ALO + sw, Alo + aoff, av);
            const size_t boff = (size_t)(n0 + r) * K + kc0 + c * 8;
            cp16(so + T_BHI + sw, Whi + boff, 16);
            cp16(so + T_BLO + sw, Wlo + boff, 16);
        }
        asm volatile("cp.async.commit_group;" ::: "memory");
    };

    issue(0);
    for (int ch = 0; ch < nch; ++ch) {
        if (ch + 1 < nch) {
            issue(ch + 1);
            asm volatile("cp.async.wait_group 1;" ::: "memory");
        } else {
            asm volatile("cp.async.wait_group 0;" ::: "memory");
        }
        __syncthreads();

        const uint32_t so = sb + (uint32_t)(ch & 1) * STAGE_BYTES;
#pragma unroll
        for (int kk = 0; kk < 64; kk += 16) {
            uint32_t ah[4][4], al[4][4];
            const int ar = (lane & 15);
            const int akb = kk + ((lane >> 4) << 3);
#pragma unroll
            for (int mi = 0; mi < 4; ++mi) {
                const int r = wm * 64 + mi * 16 + ar;
                const uint32_t off = (uint32_t)(r * 128 + ((((akb >> 3) ^ (r & 7)) & 7) << 4));
                ldsm4(ah[mi], so + T_AHI + off);
                ldsm4(al[mi], so + T_ALO + off);
            }
            uint32_t bh[2][4], bl[2][4];
            const int br = ((lane >> 4) << 3) + (lane & 7);
            const int bkb = kk + (((lane >> 3) & 1) << 3);
#pragma unroll
            for (int p = 0; p < 2; ++p) {
                const int r = wn * 32 + p * 16 + br;
                const uint32_t off = (uint32_t)(r * 128 + ((((bkb >> 3) ^ (r & 7)) & 7) << 4));
                ldsm4(bh[p], so + T_BHI + off);
                ldsm4(bl[p], so + T_BLO + off);
            }
#pragma unroll
            for (int mi = 0; mi < 4; ++mi) {
#pragma unroll
                for (int j = 0; j < 4; ++j) {
                    const uint32_t* pbh = &bh[j >> 1][(j & 1) * 2];
                    const uint32_t* pbl = &bl[j >> 1][(j & 1) * 2];
                    mma16816(acc[mi][j], ah[mi], pbh);
                    mma16816(acc[mi][j], ah[mi], pbl);
                    mma16816(acc[mi][j], al[mi], pbh);
                }
            }
        }
        __syncthreads();
    }

    // ---- epilogue ----
    const int gid  = lane >> 2;
    const int tidx = lane & 3;
#pragma unroll
    for (int mi = 0; mi < 4; ++mi) {
        const int row = m0 + wm * 64 + mi * 16 + gid;
#pragma unroll
        for (int j = 0; j < 4; ++j) {
            const int col = n0 + wn * 32 + j * 8 + tidx * 2;
            if (Ch) {
                if (row < M)
                    *(__half2*)(Ch + (size_t)row * Nc + col) =
                        __floats2half2_rn(acc[mi][j][0], acc[mi][j][1]);
                if (row + 8 < M)
                    *(__half2*)(Ch + (size_t)(row + 8) * Nc + col) =
                        __floats2half2_rn(acc[mi][j][2], acc[mi][j][3]);
            } else {
                float b0 = 0.f, b1 = 0.f;
                if (bias) { b0 = bias[col]; b1 = bias[col + 1]; }
                if (row < M)
                    *(float2*)(Cf + (size_t)row * Nc + col) =
                        make_float2(acc[mi][j][0] + b0, acc[mi][j][1] + b1);
                if (row + 8 < M)
                    *(float2*)(Cf + (size_t)(row + 8) * Nc + col) =
                        make_float2(acc[mi][j][2] + b0, acc[mi][j][3] + b1);
            }
        }
    }
}

// ---------------- host orchestration -----------------------------------------
static inline void launch_gemm_h(const __nv_bfloat16* ah, const __nv_bfloat16* al,
                                 const __nv_bfloat16* wh, const __nv_bfloat16* wl,
                                 __half* Ch, int K, int Nc) {
    dim3 grid(Nc / 128, (N_NODES + 127) / 128);
    k_gemm_mma<<<grid, 256, GEMM_SMEM>>>(ah, al, wh, wl, nullptr, Ch, nullptr, N_NODES, K, Nc);
}
static inline void launch_gemm_f(const __nv_bfloat16* ah, const __nv_bfloat16* al,
                                 const __nv_bfloat16* wh, const __nv_bfloat16* wl,
                                 const float* b, float* Cf, int K, int Nc) {
    dim3 grid(Nc / 128, (N_NODES + 127) / 128);
    k_gemm_mma<<<grid, 256, GEMM_SMEM>>>(ah, al, wh, wl, b, nullptr, Cf, N_NODES, K, Nc);
}

template <int DIM, bool GC>
static inline void launch_agg(const __half* y, __nv_bfloat16* xh, __nv_bfloat16* xl,
                              const float* bias) {
    int blocks = (N_NODES + 7) / 8;
    k_agg<DIM, GC><<<blocks, 256>>>(y, xh, xl, bias);
}

extern "C" void kernel_launch(void* const* d_in, const int* in_sizes, int n_in,
                              void* d_out, int out_size) {
    const float* features = (const float*)d_in[0];
    const int*   src      = (const int*)d_in[1];
    const int*   dst      = (const int*)d_in[2];
    const float* sw0 = (const float*)d_in[3];  const float* sb0 = (const float*)d_in[4];
    const float* gw0 = (const float*)d_in[5];  const float* gb0 = (const float*)d_in[6];
    const float* sw1 = (const float*)d_in[7];  const float* sb1 = (const float*)d_in[8];
    const float* gw1 = (const float*)d_in[9];  const float* gb1 = (const float*)d_in[10];
    const float* sw2 = (const float*)d_in[11]; const float* sb2 = (const float*)d_in[12];
    const float* gw2 = (const float*)d_in[13]; const float* gb2 = (const float*)d_in[14];
    const float* fcw = (const float*)d_in[15]; const float* fcb = (const float*)d_in[16];
    const int E = in_sizes[1];

    cudaFuncSetAttribute(k_gemm_mma, cudaFuncAttributeMaxDynamicSharedMemorySize, GEMM_SMEM);

    __half* ybuf = nullptr;
    __nv_bfloat16 *hi = nullptr, *lo = nullptr, *whi = nullptr, *wlo = nullptr;
    cudaGetSymbolAddress((void**)&ybuf, g_y);
    cudaGetSymbolAddress((void**)&hi,   g_hi);
    cudaGetSymbolAddress((void**)&lo,   g_lo);
    cudaGetSymbolAddress((void**)&whi,  g_whi);
    cudaGetSymbolAddress((void**)&wlo,  g_wlo);

    const int O_SW0 = 0,      O_GW0 = 196608, O_SW1 = 344064, O_GW1 = 442368;
    const int O_SW2 = 507904, O_GW2 = 540672, O_FC  = 557056;

    // ---- CSR build ----
    k_zero_deg<<<(N_NODES + 255) / 256, 256>>>();
    k_count<<<(E + 255) / 256, 256>>>(src, dst, E);
    k_scan<<<1, 1024>>>();
    k_scalers<<<(N_NODES + 255) / 256, 256>>>();
    k_fill<<<(E + 255) / 256, 256>>>(src, dst, E);

    // ---- converts: features + all 7 weight matrices -> split bf16 ----
    k_convert<<<(N_NODES * 512 + 255) / 256, 256>>>(features, hi, lo, N_NODES * 512);
    k_convert<<<(196608 + 255) / 256, 256>>>(sw0, whi + O_SW0, wlo + O_SW0, 196608);
    k_convert<<<(147456 + 255) / 256, 256>>>(gw0, whi + O_GW0, wlo + O_GW0, 147456);
    k_convert<<<( 98304 + 255) / 256, 256>>>(sw1, whi + O_SW1, wlo + O_SW1,  98304);
    k_convert<<<( 65536 + 255) / 256, 256>>>(gw1, whi + O_GW1, wlo + O_GW1,  65536);
    k_convert<<<( 32768 + 255) / 256, 256>>>(sw2, whi + O_SW2, wlo + O_SW2,  32768);
    k_convert<<<( 16384 + 255) / 256, 256>>>(gw2, whi + O_GW2, wlo + O_GW2,  16384);
    k_convert<<<( 16384 + 255) / 256, 256>>>(fcw, whi + O_FC,  wlo + O_FC,   16384);

    // ---- stage 0: 512 -> 384 ----
    launch_gemm_h(hi, lo, whi + O_SW0, wlo + O_SW0, ybuf, 512, 384);
    launch_agg<384, false>(ybuf, hi, lo, sb0);
    launch_gemm_h(hi, lo, whi + O_GW0, wlo + O_GW0, ybuf, 384, 384);
    launch_agg<384, true>(ybuf, hi, lo, gb0);

    // ---- stage 1: 384 -> 256 ----
    launch_gemm_h(hi, lo, whi + O_SW1, wlo + O_SW1, ybuf, 384, 256);
    launch_agg<256, false>(ybuf, hi, lo, sb1);
    launch_gemm_h(hi, lo, whi + O_GW1, wlo + O_GW1, ybuf, 256, 256);
    launch_agg<256, true>(ybuf, hi, lo, gb1);

    // ---- stage 2: 256 -> 128 ----
    launch_gemm_h(hi, lo, whi + O_SW2, wlo + O_SW2, ybuf, 256, 128);
    launch_agg<128, false>(ybuf, hi, lo, sb2);
    launch_gemm_h(hi, lo, whi + O_GW2, wlo + O_GW2, ybuf, 128, 128);
    launch_agg<128, true>(ybuf, hi, lo, gb2);

    // ---- final FC: 128 -> 128 (fp32 out, bias, no relu) ----
    launch_gemm_f(hi, lo, whi + O_FC, wlo + O_FC, fcb, (float*)d_out, 128, 128);
}